// round 9
// baseline (speedup 1.0000x reference)
#include <cuda_runtime.h>
#include <cuda_bf16.h>
#include <mma.h>
#include <math.h>
#include <stdint.h>

using namespace nvcuda;

// Problem constants
#define N_TOK 16384
#define DIM   256
#define NEXP  8
#define HID   512
#define TOPK  2
#define NASSIGN (N_TOK * TOPK)   // 32768

#define TM 128
#define MAX_TILES (NASSIGN / TM + NEXP)   // 264

// GEMM tiling: CTA tile 128x128, K chunk 32, wmma 16x16x16.
#define KB   32
#define LDA  40        // A smem leading dim (bf16): 32 + 8 pad (mult of 8 -> legal)
#define LDB  136       // B smem leading dim (bf16): 128 + 8 pad (mult of 8 -> legal)
#define LDS_ 20        // stag leading dim (fp32): mult of 4 -> LEGAL (17 was the bug)

// ================= device scratch =================
__device__ int   g_counts[NEXP];
__device__ int   g_cursor[NEXP];
__device__ int   g_off[NEXP + 1];
__device__ int   g_ntiles;
__device__ int   g_tile_e[MAX_TILES];
__device__ int   g_tile_base[MAX_TILES];
__device__ int   g_tile_rows[MAX_TILES];

__device__ int   g_topi[NASSIGN];
__device__ float g_topw[NASSIGN];
__device__ int   g_ptok[NASSIGN];
__device__ float g_pw[NASSIGN];
__device__ int   g_tok2pos[NASSIGN];

__device__ float g_h[(size_t)NASSIGN * HID];   // 64 MB post-GELU (fp32)
__device__ float g_y[(size_t)NASSIGN * DIM];   // 32 MB weighted expert outputs

// ================= kernel 0: init =================
__global__ void init_kernel() {
    int t = threadIdx.x;
    if (t < NEXP) { g_counts[t] = 0; g_cursor[t] = 0; }
}

// ================= kernel 1: gate (top-2 + softmax) =================
__global__ void gate_kernel(const float* __restrict__ x,
                            const float* __restrict__ Wg) {
    __shared__ float sWg[NEXP][DIM];
    int tid = threadIdx.x;
    for (int i = tid; i < DIM * NEXP; i += blockDim.x) {
        int e = i & (NEXP - 1);
        int d = i >> 3;
        sWg[e][d] = Wg[i];
    }
    __syncthreads();

    int warp = tid >> 5, lane = tid & 31;
    int n = blockIdx.x * 4 + warp;
    if (n >= N_TOK) return;

    float lg[NEXP];
#pragma unroll
    for (int e = 0; e < NEXP; e++) lg[e] = 0.f;
#pragma unroll
    for (int j = 0; j < 8; j++) {
        int d = lane + 32 * j;
        float xv = x[(size_t)n * DIM + d];
#pragma unroll
        for (int e = 0; e < NEXP; e++) lg[e] += xv * sWg[e][d];
    }
#pragma unroll
    for (int e = 0; e < NEXP; e++)
#pragma unroll
        for (int o = 16; o > 0; o >>= 1)
            lg[e] += __shfl_xor_sync(0xffffffffu, lg[e], o);

    if (lane == 0) {
        float m1 = lg[0]; int i1 = 0;
#pragma unroll
        for (int e = 1; e < NEXP; e++) if (lg[e] > m1) { m1 = lg[e]; i1 = e; }
        float m2 = -1e30f; int i2 = 0;
#pragma unroll
        for (int e = 0; e < NEXP; e++)
            if (e != i1 && lg[e] > m2) { m2 = lg[e]; i2 = e; }
        float p2 = expf(m2 - m1);
        float inv = 1.f / (1.f + p2);
        g_topi[2 * n + 0] = i1;  g_topw[2 * n + 0] = inv;
        g_topi[2 * n + 1] = i2;  g_topw[2 * n + 1] = p2 * inv;
        atomicAdd(&g_counts[i1], 1);
        atomicAdd(&g_counts[i2], 1);
    }
}

// ================= kernel 2: prefix + tile descriptors =================
__global__ void prep_kernel() {
    int off = 0;
    for (int e = 0; e < NEXP; e++) { g_off[e] = off; off += g_counts[e]; }
    g_off[NEXP] = off;
    int t = 0;
    for (int e = 0; e < NEXP; e++) {
        int cnt = g_counts[e];
        for (int s = 0; s < cnt; s += TM) {
            g_tile_e[t] = e; g_tile_base[t] = g_off[e] + s;
            g_tile_rows[t] = min(TM, cnt - s);
            t++;
        }
    }
    g_ntiles = t;
}

// ================= kernel 3: scatter =================
__global__ void scatter_kernel() {
    int idx = blockIdx.x * blockDim.x + threadIdx.x;
    if (idx >= NASSIGN) return;
    int e = g_topi[idx];
    int pos = g_off[e] + atomicAdd(&g_cursor[e], 1);
    g_ptok[pos] = idx >> 1;
    g_pw[pos]   = g_topw[idx];
    g_tok2pos[idx] = pos;
}

// ================= split helper: fp32 -> bf16 hi + lo =================
__device__ __forceinline__ void split_bf16(float v, __nv_bfloat16& h, __nv_bfloat16& l) {
    h = __float2bfloat16(v);
    l = __float2bfloat16(v - __bfloat162float(h));
}

// ================= kernel 4: GEMM1 (x @ w1[e]) + bias + GELU -> g_h (fp32) ====
__global__ void __launch_bounds__(256)
gemm1_mma(const float* __restrict__ x,
          const float* __restrict__ w1,
          const float* __restrict__ b1) {
    int t = blockIdx.x;
    if (t >= g_ntiles) return;
    int e = g_tile_e[t], base = g_tile_base[t], rows = g_tile_rows[t];
    int hbase = blockIdx.y * 128;

    __shared__ __align__(16) __nv_bfloat16 sAh[128 * LDA];
    __shared__ __align__(16) __nv_bfloat16 sAl[128 * LDA];
    __shared__ __align__(16) __nv_bfloat16 sBh[KB * LDB];
    __shared__ __align__(16) __nv_bfloat16 sBl[KB * LDB];
    __shared__ __align__(16) float stag[8][16][LDS_];

    int tid = threadIdx.x, wid = tid >> 5, lane = tid & 31;
    int wm = wid & 3, wn = wid >> 2;   // warp tile: rows wm*32..+31, cols wn*64..+63

    const float* w1e = w1 + (size_t)e * DIM * HID;

    wmma::fragment<wmma::accumulator, 16, 16, 16, float> acc[2][4];
#pragma unroll
    for (int i = 0; i < 2; i++)
#pragma unroll
        for (int j = 0; j < 4; j++) wmma::fill_fragment(acc[i][j], 0.f);

    int arow = tid >> 1, acol = (tid & 1) * 16;
    int tok = (arow < rows) ? g_ptok[base + arow] : -1;
    int brow = tid >> 3, bcol = (tid & 7) * 16;

    for (int c = 0; c < DIM / KB; c++) {
        int k0 = c * KB;
        __syncthreads();
#pragma unroll
        for (int q = 0; q < 16; q++) {
            float v = (tok >= 0) ? x[(size_t)tok * DIM + k0 + acol + q] : 0.f;
            __nv_bfloat16 h, l;
            split_bf16(v, h, l);
            sAh[arow * LDA + acol + q] = h;
            sAl[arow * LDA + acol + q] = l;
        }
#pragma unroll
        for (int q = 0; q < 16; q++) {
            float v = w1e[(size_t)(k0 + brow) * HID + hbase + bcol + q];
            __nv_bfloat16 h, l;
            split_bf16(v, h, l);
            sBh[brow * LDB + bcol + q] = h;
            sBl[brow * LDB + bcol + q] = l;
        }
        __syncthreads();

#pragma unroll
        for (int kk = 0; kk < KB / 16; kk++) {
            wmma::fragment<wmma::matrix_a, 16, 16, 16, __nv_bfloat16, wmma::row_major> fah[2], fal[2];
#pragma unroll
            for (int i = 0; i < 2; i++) {
                wmma::load_matrix_sync(fah[i], &sAh[(wm * 32 + i * 16) * LDA + kk * 16], LDA);
                wmma::load_matrix_sync(fal[i], &sAl[(wm * 32 + i * 16) * LDA + kk * 16], LDA);
            }
#pragma unroll
            for (int j = 0; j < 4; j++) {
                wmma::fragment<wmma::matrix_b, 16, 16, 16, __nv_bfloat16, wmma::row_major> fbh, fbl;
                wmma::load_matrix_sync(fbh, &sBh[kk * 16 * LDB + wn * 64 + j * 16], LDB);
                wmma::load_matrix_sync(fbl, &sBl[kk * 16 * LDB + wn * 64 + j * 16], LDB);
#pragma unroll
                for (int i = 0; i < 2; i++) {
                    wmma::mma_sync(acc[i][j], fah[i], fbh, acc[i][j]);
                    wmma::mma_sync(acc[i][j], fal[i], fbh, acc[i][j]);
                    wmma::mma_sync(acc[i][j], fah[i], fbl, acc[i][j]);
                }
            }
        }
    }

    // epilogue via per-warp staging (ldm = LDS_ = 20, legal): bias + exact GELU
    const float* b1e = b1 + (size_t)e * HID + hbase;
    int sr = lane >> 1, sc = (lane & 1) * 8;
#pragma unroll
    for (int i = 0; i < 2; i++)
#pragma unroll
        for (int j = 0; j < 4; j++) {
            wmma::store_matrix_sync(&stag[wid][0][0], acc[i][j], LDS_, wmma::mem_row_major);
            __syncwarp();
            int r_loc = wm * 32 + i * 16 + sr;
            if (r_loc < rows) {
                size_t ro = (size_t)(base + r_loc) * HID + hbase;
#pragma unroll
                for (int q = 0; q < 8; q++) {
                    int c_loc = wn * 64 + j * 16 + sc + q;
                    float z = stag[wid][sr][sc + q] + b1e[c_loc];
                    g_h[ro + c_loc] = 0.5f * z * (1.0f + erff(z * 0.70710678118654752f));
                }
            }
            __syncwarp();
        }
}

// ================= kernel 5: GEMM2 (g_h @ w2[e]) + bias + weight -> g_y ======
__global__ void __launch_bounds__(256)
gemm2_mma(const float* __restrict__ w2,
          const float* __restrict__ b2) {
    int t = blockIdx.x;
    if (t >= g_ntiles) return;
    int e = g_tile_e[t], base = g_tile_base[t], rows = g_tile_rows[t];
    int dbase = blockIdx.y * 128;

    __shared__ __align__(16) __nv_bfloat16 sAh[128 * LDA];
    __shared__ __align__(16) __nv_bfloat16 sAl[128 * LDA];
    __shared__ __align__(16) __nv_bfloat16 sBh[KB * LDB];
    __shared__ __align__(16) __nv_bfloat16 sBl[KB * LDB];
    __shared__ __align__(16) float stag[8][16][LDS_];

    int tid = threadIdx.x, wid = tid >> 5, lane = tid & 31;
    int wm = wid & 3, wn = wid >> 2;

    const float* w2e = w2 + (size_t)e * HID * DIM;

    wmma::fragment<wmma::accumulator, 16, 16, 16, float> acc[2][4];
#pragma unroll
    for (int i = 0; i < 2; i++)
#pragma unroll
        for (int j = 0; j < 4; j++) wmma::fill_fragment(acc[i][j], 0.f);

    int arow = tid >> 1, acol = (tid & 1) * 16;
    bool okA = (arow < rows);
    int brow = tid >> 3, bcol = (tid & 7) * 16;

    for (int c = 0; c < HID / KB; c++) {
        int k0 = c * KB;
        __syncthreads();
#pragma unroll
        for (int q = 0; q < 16; q++) {
            float v = okA ? g_h[(size_t)(base + arow) * HID + k0 + acol + q] : 0.f;
            __nv_bfloat16 h, l;
            split_bf16(v, h, l);
            sAh[arow * LDA + acol + q] = h;
            sAl[arow * LDA + acol + q] = l;
        }
#pragma unroll
        for (int q = 0; q < 16; q++) {
            float v = w2e[(size_t)(k0 + brow) * DIM + dbase + bcol + q];
            __nv_bfloat16 h, l;
            split_bf16(v, h, l);
            sBh[brow * LDB + bcol + q] = h;
            sBl[brow * LDB + bcol + q] = l;
        }
        __syncthreads();

#pragma unroll
        for (int kk = 0; kk < KB / 16; kk++) {
            wmma::fragment<wmma::matrix_a, 16, 16, 16, __nv_bfloat16, wmma::row_major> fah[2], fal[2];
#pragma unroll
            for (int i = 0; i < 2; i++) {
                wmma::load_matrix_sync(fah[i], &sAh[(wm * 32 + i * 16) * LDA + kk * 16], LDA);
                wmma::load_matrix_sync(fal[i], &sAl[(wm * 32 + i * 16) * LDA + kk * 16], LDA);
            }
#pragma unroll
            for (int j = 0; j < 4; j++) {
                wmma::fragment<wmma::matrix_b, 16, 16, 16, __nv_bfloat16, wmma::row_major> fbh, fbl;
                wmma::load_matrix_sync(fbh, &sBh[kk * 16 * LDB + wn * 64 + j * 16], LDB);
                wmma::load_matrix_sync(fbl, &sBl[kk * 16 * LDB + wn * 64 + j * 16], LDB);
#pragma unroll
                for (int i = 0; i < 2; i++) {
                    wmma::mma_sync(acc[i][j], fah[i], fbh, acc[i][j]);
                    wmma::mma_sync(acc[i][j], fal[i], fbh, acc[i][j]);
                    wmma::mma_sync(acc[i][j], fah[i], fbl, acc[i][j]);
                }
            }
        }
    }

    const float* b2e = b2 + (size_t)e * DIM + dbase;
    int sr = lane >> 1, sc = (lane & 1) * 8;
#pragma unroll
    for (int i = 0; i < 2; i++)
#pragma unroll
        for (int j = 0; j < 4; j++) {
            wmma::store_matrix_sync(&stag[wid][0][0], acc[i][j], LDS_, wmma::mem_row_major);
            __syncwarp();
            int r_loc = wm * 32 + i * 16 + sr;
            if (r_loc < rows) {
                float wgt = g_pw[base + r_loc];
                size_t ro = (size_t)(base + r_loc) * DIM + dbase;
#pragma unroll
                for (int q = 0; q < 8; q++) {
                    int c_loc = wn * 64 + j * 16 + sc + q;
                    g_y[ro + c_loc] = (stag[wid][sr][sc + q] + b2e[c_loc]) * wgt;
                }
            }
            __syncwarp();
        }
}

// ================= kernel 6: deterministic combine =================
__global__ void combine_kernel(float* __restrict__ out) {
    int idx = blockIdx.x * blockDim.x + threadIdx.x;
    if (idx >= N_TOK * (DIM / 4)) return;
    int n = idx >> 6, q = idx & 63;
    int p0 = g_tok2pos[2 * n + 0];
    int p1 = g_tok2pos[2 * n + 1];
    float4 a = ((const float4*)&g_y[(size_t)p0 * DIM])[q];
    float4 b = ((const float4*)&g_y[(size_t)p1 * DIM])[q];
    ((float4*)out)[(size_t)n * 64 + q] =
        make_float4(a.x + b.x, a.y + b.y, a.z + b.z, a.w + b.w);
}

// ================= launch =================
extern "C" void kernel_launch(void* const* d_in, const int* in_sizes, int n_in,
                              void* d_out, int out_size) {
    const float* x  = (const float*)d_in[0];
    const float* Wg = (const float*)d_in[1];
    const float* w1 = (const float*)d_in[2];
    const float* b1 = (const float*)d_in[3];
    const float* w2 = (const float*)d_in[4];
    const float* b2 = (const float*)d_in[5];
    float* out = (float*)d_out;

    init_kernel<<<1, 32>>>();
    gate_kernel<<<N_TOK / 4, 128>>>(x, Wg);
    prep_kernel<<<1, 1>>>();
    scatter_kernel<<<NASSIGN / 256, 256>>>();
    gemm1_mma<<<dim3(MAX_TILES, HID / 128), 256>>>(x, w1, b1);
    gemm2_mma<<<dim3(MAX_TILES, DIM / 128), 256>>>(w2, b2);
    combine_kernel<<<(N_TOK * (DIM / 4)) / 256, 256>>>(out);
}

// round 12
// speedup vs baseline: 1.5956x; 1.5956x over previous
#include <cuda_runtime.h>
#include <cuda_bf16.h>
#include <mma.h>
#include <math.h>
#include <stdint.h>

using namespace nvcuda;

// Problem constants
#define N_TOK 16384
#define DIM   256
#define NEXP  8
#define HID   512
#define TOPK  2
#define NASSIGN (N_TOK * TOPK)   // 32768

#define TM 128
#define MAX_TILES (NASSIGN / TM + NEXP)   // 264
#define HALF_TILES 136
#define HROWS 18432                       // per-half h rows (>= 136*128)

// GEMM tiling: CTA tile 128x128, K chunk 32, wmma 16x16x16.
#define KB   32
#define LDA  40        // A smem leading dim (bf16)
#define LDB  136       // B smem leading dim (bf16)
#define LDS_ 20        // stag leading dim (fp32), multiple of 4

// ================= device scratch (~92 MB) =================
__device__ int   g_counts[NEXP];
__device__ int   g_cursor[NEXP];
__device__ int   g_off[NEXP + 1];
__device__ int   g_ntiles;
__device__ int   g_tile_e[MAX_TILES];
__device__ int   g_tile_base[MAX_TILES];
__device__ int   g_tile_rows[MAX_TILES];

__device__ int   g_topi[NASSIGN];
__device__ float g_topw[NASSIGN];
__device__ int   g_ptok[NASSIGN];
__device__ float g_pw[NASSIGN];
__device__ int   g_tok2pos[NASSIGN];

__device__ __nv_bfloat16 g_xhi[(size_t)N_TOK * DIM];
__device__ __nv_bfloat16 g_xlo[(size_t)N_TOK * DIM];
__device__ __nv_bfloat16 g_w1hi[(size_t)NEXP * DIM * HID];  // [E][D][H]
__device__ __nv_bfloat16 g_w1lo[(size_t)NEXP * DIM * HID];
__device__ __nv_bfloat16 g_w2hi[(size_t)NEXP * HID * DIM];  // [E][H][D]
__device__ __nv_bfloat16 g_w2lo[(size_t)NEXP * HID * DIM];
__device__ float g_h[(size_t)HROWS * HID];                  // per-half fp32
__device__ float g_y[(size_t)NASSIGN * DIM];

// ================= kernel 0: init =================
__global__ void init_kernel() {
    int t = threadIdx.x;
    if (t < NEXP) { g_counts[t] = 0; g_cursor[t] = 0; }
}

// ================= kernel 1: gate (top-2 + softmax) =================
__global__ void gate_kernel(const float* __restrict__ x,
                            const float* __restrict__ Wg) {
    __shared__ float sWg[NEXP][DIM];
    int tid = threadIdx.x;
    for (int i = tid; i < DIM * NEXP; i += blockDim.x) {
        int e = i & (NEXP - 1);
        int d = i >> 3;
        sWg[e][d] = Wg[i];
    }
    __syncthreads();

    int warp = tid >> 5, lane = tid & 31;
    int n = blockIdx.x * 4 + warp;
    if (n >= N_TOK) return;

    float lg[NEXP];
#pragma unroll
    for (int e = 0; e < NEXP; e++) lg[e] = 0.f;
#pragma unroll
    for (int j = 0; j < 8; j++) {
        int d = lane + 32 * j;
        float xv = x[(size_t)n * DIM + d];
#pragma unroll
        for (int e = 0; e < NEXP; e++) lg[e] += xv * sWg[e][d];
    }
#pragma unroll
    for (int e = 0; e < NEXP; e++)
#pragma unroll
        for (int o = 16; o > 0; o >>= 1)
            lg[e] += __shfl_xor_sync(0xffffffffu, lg[e], o);

    if (lane == 0) {
        float m1 = lg[0]; int i1 = 0;
#pragma unroll
        for (int e = 1; e < NEXP; e++) if (lg[e] > m1) { m1 = lg[e]; i1 = e; }
        float m2 = -1e30f; int i2 = 0;
#pragma unroll
        for (int e = 0; e < NEXP; e++)
            if (e != i1 && lg[e] > m2) { m2 = lg[e]; i2 = e; }
        float p2 = expf(m2 - m1);
        float inv = 1.f / (1.f + p2);
        g_topi[2 * n + 0] = i1;  g_topw[2 * n + 0] = inv;
        g_topi[2 * n + 1] = i2;  g_topw[2 * n + 1] = p2 * inv;
        atomicAdd(&g_counts[i1], 1);
        atomicAdd(&g_counts[i2], 1);
    }
}

// ================= kernel 2: prefix + tile descriptors =================
__global__ void prep_kernel() {
    int off = 0;
    for (int e = 0; e < NEXP; e++) { g_off[e] = off; off += g_counts[e]; }
    g_off[NEXP] = off;
    int t = 0;
    for (int e = 0; e < NEXP; e++) {
        int cnt = g_counts[e];
        for (int s = 0; s < cnt; s += TM) {
            g_tile_e[t] = e; g_tile_base[t] = g_off[e] + s;
            g_tile_rows[t] = min(TM, cnt - s);
            t++;
        }
    }
    g_ntiles = t;
}

// ================= kernel 3: scatter =================
__global__ void scatter_kernel() {
    int idx = blockIdx.x * blockDim.x + threadIdx.x;
    if (idx >= NASSIGN) return;
    int e = g_topi[idx];
    int pos = g_off[e] + atomicAdd(&g_cursor[e], 1);
    g_ptok[pos] = idx >> 1;
    g_pw[pos]   = g_topw[idx];
    g_tok2pos[idx] = pos;
}

// ===== split helper =====
__device__ __forceinline__ void split8(const float* v,
                                       __nv_bfloat16* h, __nv_bfloat16* l) {
#pragma unroll
    for (int i = 0; i < 8; i++) {
        h[i] = __float2bfloat16(v[i]);
        l[i] = __float2bfloat16(v[i] - __bfloat162float(h[i]));
    }
}

// ================= conv kernels: destinations referenced INSIDE device code ==
// (passing __device__ globals as host-side kernel args was the root cause of
//  every rel=1.0 failure — host shadow symbol != device pointer)
__global__ void conv_x_kernel(const float* __restrict__ src) {
    int idx = blockIdx.x * blockDim.x + threadIdx.x;
    if (idx >= N_TOK * DIM / 8) return;
    size_t b8 = (size_t)idx * 8;
    float4 a = *(const float4*)&src[b8];
    float4 b = *(const float4*)&src[b8 + 4];
    float v[8] = {a.x, a.y, a.z, a.w, b.x, b.y, b.z, b.w};
    __align__(16) __nv_bfloat16 h[8], l[8];
    split8(v, h, l);
    *(uint4*)&g_xhi[b8] = *(uint4*)h;
    *(uint4*)&g_xlo[b8] = *(uint4*)l;
}

__global__ void conv_w1_kernel(const float* __restrict__ src) {
    int idx = blockIdx.x * blockDim.x + threadIdx.x;
    if (idx >= NEXP * DIM * HID / 8) return;
    size_t b8 = (size_t)idx * 8;
    float4 a = *(const float4*)&src[b8];
    float4 b = *(const float4*)&src[b8 + 4];
    float v[8] = {a.x, a.y, a.z, a.w, b.x, b.y, b.z, b.w};
    __align__(16) __nv_bfloat16 h[8], l[8];
    split8(v, h, l);
    *(uint4*)&g_w1hi[b8] = *(uint4*)h;
    *(uint4*)&g_w1lo[b8] = *(uint4*)l;
}

__global__ void conv_w2_kernel(const float* __restrict__ src) {
    int idx = blockIdx.x * blockDim.x + threadIdx.x;
    if (idx >= NEXP * HID * DIM / 8) return;
    size_t b8 = (size_t)idx * 8;
    float4 a = *(const float4*)&src[b8];
    float4 b = *(const float4*)&src[b8 + 4];
    float v[8] = {a.x, a.y, a.z, a.w, b.x, b.y, b.z, b.w};
    __align__(16) __nv_bfloat16 h[8], l[8];
    split8(v, h, l);
    *(uint4*)&g_w2hi[b8] = *(uint4*)h;
    *(uint4*)&g_w2lo[b8] = *(uint4*)l;
}

// ================= half-range helper =================
__device__ __forceinline__ bool tile_range(int half, int bx,
                                           int& t, int& h0pos) {
    int Hs = (g_ntiles + 1) >> 1;
    int t0 = half ? Hs : 0;
    int tend = half ? g_ntiles : Hs;
    t = t0 + bx;
    if (t >= tend) return false;
    h0pos = g_tile_base[t0];
    return true;
}

// ================= kernel: GEMM1 (x @ w1[e]) + bias + GELU -> g_h ===========
__global__ void __launch_bounds__(256)
gemm1_mma(const float* __restrict__ b1, int half) {
    int t, h0pos;
    if (!tile_range(half, blockIdx.x, t, h0pos)) return;
    int e = g_tile_e[t], base = g_tile_base[t], rows = g_tile_rows[t];
    int hbase = blockIdx.y * 128;

    __shared__ __align__(16) __nv_bfloat16 sAh[128 * LDA];
    __shared__ __align__(16) __nv_bfloat16 sAl[128 * LDA];
    __shared__ __align__(16) __nv_bfloat16 sBh[KB * LDB];
    __shared__ __align__(16) __nv_bfloat16 sBl[KB * LDB];
    __shared__ __align__(16) float stag[8][16][LDS_];

    int tid = threadIdx.x, wid = tid >> 5, lane = tid & 31;
    int wm = wid & 3, wn = wid >> 2;

    const __nv_bfloat16* w1h = g_w1hi + (size_t)e * DIM * HID;
    const __nv_bfloat16* w1l = g_w1lo + (size_t)e * DIM * HID;

    wmma::fragment<wmma::accumulator, 16, 16, 16, float> acc[2][4];
#pragma unroll
    for (int i = 0; i < 2; i++)
#pragma unroll
        for (int j = 0; j < 4; j++) wmma::fill_fragment(acc[i][j], 0.f);

    int arow = tid >> 1, acol = (tid & 1) * 16;
    int tok = (arow < rows) ? g_ptok[base + arow] : -1;
    int brow = tid >> 3, bcol = (tid & 7) * 16;

    for (int c = 0; c < DIM / KB; c++) {
        int k0 = c * KB;
        __syncthreads();
        {
            uint4 vh0 = make_uint4(0, 0, 0, 0), vh1 = vh0, vl0 = vh0, vl1 = vh0;
            if (tok >= 0) {
                size_t s = (size_t)tok * DIM + k0 + acol;
                vh0 = *(const uint4*)&g_xhi[s];
                vh1 = *(const uint4*)&g_xhi[s + 8];
                vl0 = *(const uint4*)&g_xlo[s];
                vl1 = *(const uint4*)&g_xlo[s + 8];
            }
            *(uint4*)&sAh[arow * LDA + acol]     = vh0;
            *(uint4*)&sAh[arow * LDA + acol + 8] = vh1;
            *(uint4*)&sAl[arow * LDA + acol]     = vl0;
            *(uint4*)&sAl[arow * LDA + acol + 8] = vl1;
        }
        {
            size_t s = (size_t)(k0 + brow) * HID + hbase + bcol;
            *(uint4*)&sBh[brow * LDB + bcol]     = *(const uint4*)&w1h[s];
            *(uint4*)&sBh[brow * LDB + bcol + 8] = *(const uint4*)&w1h[s + 8];
            *(uint4*)&sBl[brow * LDB + bcol]     = *(const uint4*)&w1l[s];
            *(uint4*)&sBl[brow * LDB + bcol + 8] = *(const uint4*)&w1l[s + 8];
        }
        __syncthreads();

#pragma unroll
        for (int kk = 0; kk < KB / 16; kk++) {
            wmma::fragment<wmma::matrix_a, 16, 16, 16, __nv_bfloat16, wmma::row_major> fah[2], fal[2];
#pragma unroll
            for (int i = 0; i < 2; i++) {
                wmma::load_matrix_sync(fah[i], &sAh[(wm * 32 + i * 16) * LDA + kk * 16], LDA);
                wmma::load_matrix_sync(fal[i], &sAl[(wm * 32 + i * 16) * LDA + kk * 16], LDA);
            }
#pragma unroll
            for (int j = 0; j < 4; j++) {
                wmma::fragment<wmma::matrix_b, 16, 16, 16, __nv_bfloat16, wmma::row_major> fbh, fbl;
                wmma::load_matrix_sync(fbh, &sBh[kk * 16 * LDB + wn * 64 + j * 16], LDB);
                wmma::load_matrix_sync(fbl, &sBl[kk * 16 * LDB + wn * 64 + j * 16], LDB);
#pragma unroll
                for (int i = 0; i < 2; i++) {
                    wmma::mma_sync(acc[i][j], fah[i], fbh, acc[i][j]);
                    wmma::mma_sync(acc[i][j], fal[i], fbh, acc[i][j]);
                    wmma::mma_sync(acc[i][j], fah[i], fbl, acc[i][j]);
                }
            }
        }
    }

    const float* b1e = b1 + (size_t)e * HID + hbase;
    int sr = lane >> 1, sc = (lane & 1) * 8;
#pragma unroll
    for (int i = 0; i < 2; i++)
#pragma unroll
        for (int j = 0; j < 4; j++) {
            wmma::store_matrix_sync(&stag[wid][0][0], acc[i][j], LDS_, wmma::mem_row_major);
            __syncwarp();
            int r_loc = wm * 32 + i * 16 + sr;
            if (r_loc < rows) {
                int c0 = wn * 64 + j * 16 + sc;
                size_t ro = (size_t)(base - h0pos + r_loc) * HID + hbase + c0;
                __align__(16) float v[8];
#pragma unroll
                for (int q = 0; q < 8; q++) {
                    float z = stag[wid][sr][sc + q] + b1e[c0 + q];
                    v[q] = 0.5f * z * (1.0f + erff(z * 0.70710678118654752f));
                }
                *(float4*)&g_h[ro]     = ((float4*)v)[0];
                *(float4*)&g_h[ro + 4] = ((float4*)v)[1];
            }
            __syncwarp();
        }
}

// ================= kernel: GEMM2 (g_h @ w2[e]) + bias + weight -> g_y ========
__global__ void __launch_bounds__(256)
gemm2_mma(const float* __restrict__ b2, int half) {
    int t, h0pos;
    if (!tile_range(half, blockIdx.x, t, h0pos)) return;
    int e = g_tile_e[t], base = g_tile_base[t], rows = g_tile_rows[t];
    int dbase = blockIdx.y * 128;

    __shared__ __align__(16) __nv_bfloat16 sAh[128 * LDA];
    __shared__ __align__(16) __nv_bfloat16 sAl[128 * LDA];
    __shared__ __align__(16) __nv_bfloat16 sBh[KB * LDB];
    __shared__ __align__(16) __nv_bfloat16 sBl[KB * LDB];
    __shared__ __align__(16) float stag[8][16][LDS_];

    int tid = threadIdx.x, wid = tid >> 5, lane = tid & 31;
    int wm = wid & 3, wn = wid >> 2;

    const __nv_bfloat16* w2h = g_w2hi + (size_t)e * HID * DIM;
    const __nv_bfloat16* w2l = g_w2lo + (size_t)e * HID * DIM;

    wmma::fragment<wmma::accumulator, 16, 16, 16, float> acc[2][4];
#pragma unroll
    for (int i = 0; i < 2; i++)
#pragma unroll
        for (int j = 0; j < 4; j++) wmma::fill_fragment(acc[i][j], 0.f);

    int arow = tid >> 1, acol = (tid & 1) * 16;
    bool okA = (arow < rows);
    int brow = tid >> 3, bcol = (tid & 7) * 16;

    for (int c = 0; c < HID / KB; c++) {
        int k0 = c * KB;
        __syncthreads();
        {
            __align__(16) __nv_bfloat16 hh[16], ll[16];
            if (okA) {
                size_t s = (size_t)(base - h0pos + arow) * HID + k0 + acol;
#pragma unroll
                for (int g4 = 0; g4 < 4; g4++) {
                    float4 f = *(const float4*)&g_h[s + g4 * 4];
                    float vv[4] = {f.x, f.y, f.z, f.w};
#pragma unroll
                    for (int q = 0; q < 4; q++) {
                        __nv_bfloat16 h = __float2bfloat16(vv[q]);
                        hh[g4 * 4 + q] = h;
                        ll[g4 * 4 + q] = __float2bfloat16(vv[q] - __bfloat162float(h));
                    }
                }
            } else {
#pragma unroll
                for (int q = 0; q < 16; q++) { hh[q] = __float2bfloat16(0.f); ll[q] = hh[q]; }
            }
            *(uint4*)&sAh[arow * LDA + acol]     = ((uint4*)hh)[0];
            *(uint4*)&sAh[arow * LDA + acol + 8] = ((uint4*)hh)[1];
            *(uint4*)&sAl[arow * LDA + acol]     = ((uint4*)ll)[0];
            *(uint4*)&sAl[arow * LDA + acol + 8] = ((uint4*)ll)[1];
        }
        {
            size_t s = (size_t)(k0 + brow) * DIM + dbase + bcol;
            *(uint4*)&sBh[brow * LDB + bcol]     = *(const uint4*)&w2h[s];
            *(uint4*)&sBh[brow * LDB + bcol + 8] = *(const uint4*)&w2h[s + 8];
            *(uint4*)&sBl[brow * LDB + bcol]     = *(const uint4*)&w2l[s];
            *(uint4*)&sBl[brow * LDB + bcol + 8] = *(const uint4*)&w2l[s + 8];
        }
        __syncthreads();

#pragma unroll
        for (int kk = 0; kk < KB / 16; kk++) {
            wmma::fragment<wmma::matrix_a, 16, 16, 16, __nv_bfloat16, wmma::row_major> fah[2], fal[2];
#pragma unroll
            for (int i = 0; i < 2; i++) {
                wmma::load_matrix_sync(fah[i], &sAh[(wm * 32 + i * 16) * LDA + kk * 16], LDA);
                wmma::load_matrix_sync(fal[i], &sAl[(wm * 32 + i * 16) * LDA + kk * 16], LDA);
            }
#pragma unroll
            for (int j = 0; j < 4; j++) {
                wmma::fragment<wmma::matrix_b, 16, 16, 16, __nv_bfloat16, wmma::row_major> fbh, fbl;
                wmma::load_matrix_sync(fbh, &sBh[kk * 16 * LDB + wn * 64 + j * 16], LDB);
                wmma::load_matrix_sync(fbl, &sBl[kk * 16 * LDB + wn * 64 + j * 16], LDB);
#pragma unroll
                for (int i = 0; i < 2; i++) {
                    wmma::mma_sync(acc[i][j], fah[i], fbh, acc[i][j]);
                    wmma::mma_sync(acc[i][j], fal[i], fbh, acc[i][j]);
                    wmma::mma_sync(acc[i][j], fah[i], fbl, acc[i][j]);
                }
            }
        }
    }

    const float* b2e = b2 + (size_t)e * DIM + dbase;
    int sr = lane >> 1, sc = (lane & 1) * 8;
#pragma unroll
    for (int i = 0; i < 2; i++)
#pragma unroll
        for (int j = 0; j < 4; j++) {
            wmma::store_matrix_sync(&stag[wid][0][0], acc[i][j], LDS_, wmma::mem_row_major);
            __syncwarp();
            int r_loc = wm * 32 + i * 16 + sr;
            if (r_loc < rows) {
                float wgt = g_pw[base + r_loc];
                int c0 = wn * 64 + j * 16 + sc;
                size_t ro = (size_t)(base + r_loc) * DIM + dbase + c0;
                __align__(16) float v[8];
#pragma unroll
                for (int q = 0; q < 8; q++)
                    v[q] = (stag[wid][sr][sc + q] + b2e[c0 + q]) * wgt;
                *(float4*)&g_y[ro]     = ((float4*)v)[0];
                *(float4*)&g_y[ro + 4] = ((float4*)v)[1];
            }
            __syncwarp();
        }
}

// ================= kernel: deterministic combine =================
__global__ void combine_kernel(float* __restrict__ out) {
    int idx = blockIdx.x * blockDim.x + threadIdx.x;
    if (idx >= N_TOK * (DIM / 4)) return;
    int n = idx >> 6, q = idx & 63;
    int p0 = g_tok2pos[2 * n + 0];
    int p1 = g_tok2pos[2 * n + 1];
    float4 a = ((const float4*)&g_y[(size_t)p0 * DIM])[q];
    float4 b = ((const float4*)&g_y[(size_t)p1 * DIM])[q];
    ((float4*)out)[(size_t)n * 64 + q] =
        make_float4(a.x + b.x, a.y + b.y, a.z + b.z, a.w + b.w);
}

// ================= launch =================
extern "C" void kernel_launch(void* const* d_in, const int* in_sizes, int n_in,
                              void* d_out, int out_size) {
    const float* x  = (const float*)d_in[0];
    const float* Wg = (const float*)d_in[1];
    const float* w1 = (const float*)d_in[2];
    const float* b1 = (const float*)d_in[3];
    const float* w2 = (const float*)d_in[4];
    const float* b2 = (const float*)d_in[5];
    float* out = (float*)d_out;

    init_kernel<<<1, 32>>>();
    gate_kernel<<<N_TOK / 4, 128>>>(x, Wg);
    prep_kernel<<<1, 1>>>();
    scatter_kernel<<<NASSIGN / 256, 256>>>();
    conv_x_kernel<<<(N_TOK * DIM / 8) / 256, 256>>>(x);
    conv_w1_kernel<<<(NEXP * DIM * HID / 8) / 256, 256>>>(w1);
    conv_w2_kernel<<<(NEXP * HID * DIM / 8) / 256, 256>>>(w2);
    for (int half = 0; half < 2; half++) {
        gemm1_mma<<<dim3(HALF_TILES, HID / 128), 256>>>(b1, half);
        gemm2_mma<<<dim3(HALF_TILES, DIM / 128), 256>>>(b2, half);
    }
    combine_kernel<<<(N_TOK * (DIM / 4)) / 256, 256>>>(out);
}

// round 13
// speedup vs baseline: 1.6865x; 1.0570x over previous
#include <cuda_runtime.h>
#include <cuda_bf16.h>
#include <mma.h>
#include <math.h>
#include <stdint.h>

using namespace nvcuda;

// Problem constants
#define N_TOK 16384
#define DIM   256
#define NEXP  8
#define HID   512
#define TOPK  2
#define NASSIGN (N_TOK * TOPK)            // 32768
#define NPAD (NASSIGN + NEXP * 128)       // 33792 padded positions
#define MAX_TILES (NPAD / 128)            // 264
#define HALF_TILES 136
#define HROWS 17408                       // per-half h rows (136*128)

// GEMM tiling: CTA tile 128x128, K chunk 32, wmma 16x16x16.
#define KB   32
#define LDA  40        // A smem leading dim (bf16)
#define LDB  136       // B smem leading dim (bf16)

// ================= device scratch =================
__device__ int   g_counts[NEXP];
__device__ int   g_cursor[NEXP];
__device__ int   g_off[NEXP + 1];
__device__ int   g_ntiles;
__device__ int   g_tile_e[MAX_TILES];
__device__ int   g_tile_base[MAX_TILES];
__device__ int   g_tile_rows[MAX_TILES];

__device__ int   g_topi[NASSIGN];
__device__ float g_topw[NASSIGN];
__device__ int   g_ptok[NPAD];
__device__ int   g_tok2pos[NASSIGN];

__device__ __nv_bfloat16 g_xhi[(size_t)N_TOK * DIM];
__device__ __nv_bfloat16 g_xlo[(size_t)N_TOK * DIM];
__device__ __nv_bfloat16 g_w1hi[(size_t)NEXP * DIM * HID];  // [E][D][H]
__device__ __nv_bfloat16 g_w1lo[(size_t)NEXP * DIM * HID];
__device__ __nv_bfloat16 g_w2hi[(size_t)NEXP * HID * DIM];  // [E][H][D]
__device__ __nv_bfloat16 g_w2lo[(size_t)NEXP * HID * DIM];
// g_h: raw fp32 from GEMM1, then packed (bf16 hi | bf16 lo) in place by gelu
__device__ unsigned int g_h[(size_t)HROWS * HID];
__device__ float g_y[(size_t)NPAD * DIM];

// ================= kernel 0: init =================
__global__ void init_kernel() {
    int t = threadIdx.x;
    if (t < NEXP) { g_counts[t] = 0; g_cursor[t] = 0; }
}

// ================= kernel 1: gate (top-2 + softmax) =================
__global__ void gate_kernel(const float* __restrict__ x,
                            const float* __restrict__ Wg) {
    __shared__ float sWg[NEXP][DIM];
    int tid = threadIdx.x;
    for (int i = tid; i < DIM * NEXP; i += blockDim.x) {
        int e = i & (NEXP - 1);
        int d = i >> 3;
        sWg[e][d] = Wg[i];
    }
    __syncthreads();

    int warp = tid >> 5, lane = tid & 31;
    int n = blockIdx.x * 4 + warp;
    if (n >= N_TOK) return;

    float lg[NEXP];
#pragma unroll
    for (int e = 0; e < NEXP; e++) lg[e] = 0.f;
#pragma unroll
    for (int j = 0; j < 8; j++) {
        int d = lane + 32 * j;
        float xv = x[(size_t)n * DIM + d];
#pragma unroll
        for (int e = 0; e < NEXP; e++) lg[e] += xv * sWg[e][d];
    }
#pragma unroll
    for (int e = 0; e < NEXP; e++)
#pragma unroll
        for (int o = 16; o > 0; o >>= 1)
            lg[e] += __shfl_xor_sync(0xffffffffu, lg[e], o);

    if (lane == 0) {
        float m1 = lg[0]; int i1 = 0;
#pragma unroll
        for (int e = 1; e < NEXP; e++) if (lg[e] > m1) { m1 = lg[e]; i1 = e; }
        float m2 = -1e30f; int i2 = 0;
#pragma unroll
        for (int e = 0; e < NEXP; e++)
            if (e != i1 && lg[e] > m2) { m2 = lg[e]; i2 = e; }
        float p2 = expf(m2 - m1);
        float inv = 1.f / (1.f + p2);
        g_topi[2 * n + 0] = i1;  g_topw[2 * n + 0] = inv;
        g_topi[2 * n + 1] = i2;  g_topw[2 * n + 1] = p2 * inv;
        atomicAdd(&g_counts[i1], 1);
        atomicAdd(&g_counts[i2], 1);
    }
}

// ================= kernel 2: prefix (128-aligned) + tile descriptors ========
__global__ void prep_kernel() {
    int off = 0;
    for (int e = 0; e < NEXP; e++) {
        g_off[e] = off;
        off += (g_counts[e] + 127) & ~127;   // 128-align each segment
    }
    g_off[NEXP] = off;
    int t = 0;
    for (int e = 0; e < NEXP; e++) {
        int cnt = g_counts[e];
        for (int s = 0; s < cnt; s += 128) {
            g_tile_e[t] = e;
            g_tile_base[t] = g_off[e] + s;
            g_tile_rows[t] = min(128, cnt - s);
            t++;
        }
    }
    g_ntiles = t;
}

// ================= kernel 3: scatter =================
__global__ void scatter_kernel() {
    int idx = blockIdx.x * blockDim.x + threadIdx.x;
    if (idx >= NASSIGN) return;
    int e = g_topi[idx];
    int pos = g_off[e] + atomicAdd(&g_cursor[e], 1);
    g_ptok[pos] = idx >> 1;
    g_tok2pos[idx] = pos;
}

// ===== split helper =====
__device__ __forceinline__ void split8(const float* v,
                                       __nv_bfloat16* h, __nv_bfloat16* l) {
#pragma unroll
    for (int i = 0; i < 8; i++) {
        h[i] = __float2bfloat16(v[i]);
        l[i] = __float2bfloat16(v[i] - __bfloat162float(h[i]));
    }
}

// ================= conv kernels (globals referenced INSIDE device code) ======
__global__ void conv_x_kernel(const float* __restrict__ src) {
    int idx = blockIdx.x * blockDim.x + threadIdx.x;
    if (idx >= N_TOK * DIM / 8) return;
    size_t b8 = (size_t)idx * 8;
    float4 a = *(const float4*)&src[b8];
    float4 b = *(const float4*)&src[b8 + 4];
    float v[8] = {a.x, a.y, a.z, a.w, b.x, b.y, b.z, b.w};
    __align__(16) __nv_bfloat16 h[8], l[8];
    split8(v, h, l);
    *(uint4*)&g_xhi[b8] = *(uint4*)h;
    *(uint4*)&g_xlo[b8] = *(uint4*)l;
}

__global__ void conv_w1_kernel(const float* __restrict__ src) {
    int idx = blockIdx.x * blockDim.x + threadIdx.x;
    if (idx >= NEXP * DIM * HID / 8) return;
    size_t b8 = (size_t)idx * 8;
    float4 a = *(const float4*)&src[b8];
    float4 b = *(const float4*)&src[b8 + 4];
    float v[8] = {a.x, a.y, a.z, a.w, b.x, b.y, b.z, b.w};
    __align__(16) __nv_bfloat16 h[8], l[8];
    split8(v, h, l);
    *(uint4*)&g_w1hi[b8] = *(uint4*)h;
    *(uint4*)&g_w1lo[b8] = *(uint4*)l;
}

__global__ void conv_w2_kernel(const float* __restrict__ src) {
    int idx = blockIdx.x * blockDim.x + threadIdx.x;
    if (idx >= NEXP * HID * DIM / 8) return;
    size_t b8 = (size_t)idx * 8;
    float4 a = *(const float4*)&src[b8];
    float4 b = *(const float4*)&src[b8 + 4];
    float v[8] = {a.x, a.y, a.z, a.w, b.x, b.y, b.z, b.w};
    __align__(16) __nv_bfloat16 h[8], l[8];
    split8(v, h, l);
    *(uint4*)&g_w2hi[b8] = *(uint4*)h;
    *(uint4*)&g_w2lo[b8] = *(uint4*)l;
}

// ================= half-range helper =================
__device__ __forceinline__ bool tile_range(int half, int bx,
                                           int& t, int& h0pos) {
    int Hs = (g_ntiles + 1) >> 1;
    int t0 = half ? Hs : 0;
    int tend = half ? g_ntiles : Hs;
    t = t0 + bx;
    if (t >= tend) return false;
    h0pos = g_tile_base[t0];
    return true;
}
__device__ __forceinline__ void half_rows(int half, int& h0, int& hend) {
    int Hs = (g_ntiles + 1) >> 1;
    h0 = half ? g_tile_base[Hs] : 0;
    hend = half ? g_off[NEXP] : g_tile_base[Hs];
}

// ================= GEMM1: x @ w1[e] -> raw fp32 g_h (direct frag stores) =====
__global__ void __launch_bounds__(256)
gemm1_mma(int half) {
    int t, h0pos;
    if (!tile_range(half, blockIdx.x, t, h0pos)) return;
    int e = g_tile_e[t], base = g_tile_base[t], rows = g_tile_rows[t];
    int hbase = blockIdx.y * 128;

    __shared__ __align__(16) __nv_bfloat16 sAh[128 * LDA];
    __shared__ __align__(16) __nv_bfloat16 sAl[128 * LDA];
    __shared__ __align__(16) __nv_bfloat16 sBh[KB * LDB];
    __shared__ __align__(16) __nv_bfloat16 sBl[KB * LDB];

    int tid = threadIdx.x, wid = tid >> 5;
    int wm = wid & 3, wn = wid >> 2;

    const __nv_bfloat16* w1h = g_w1hi + (size_t)e * DIM * HID;
    const __nv_bfloat16* w1l = g_w1lo + (size_t)e * DIM * HID;

    wmma::fragment<wmma::accumulator, 16, 16, 16, float> acc[2][4];
#pragma unroll
    for (int i = 0; i < 2; i++)
#pragma unroll
        for (int j = 0; j < 4; j++) wmma::fill_fragment(acc[i][j], 0.f);

    int arow = tid >> 1, acol = (tid & 1) * 16;
    int tok = (arow < rows) ? g_ptok[base + arow] : -1;
    int brow = tid >> 3, bcol = (tid & 7) * 16;

    for (int c = 0; c < DIM / KB; c++) {
        int k0 = c * KB;
        __syncthreads();
        {
            uint4 vh0 = make_uint4(0, 0, 0, 0), vh1 = vh0, vl0 = vh0, vl1 = vh0;
            if (tok >= 0) {
                size_t s = (size_t)tok * DIM + k0 + acol;
                vh0 = *(const uint4*)&g_xhi[s];
                vh1 = *(const uint4*)&g_xhi[s + 8];
                vl0 = *(const uint4*)&g_xlo[s];
                vl1 = *(const uint4*)&g_xlo[s + 8];
            }
            *(uint4*)&sAh[arow * LDA + acol]     = vh0;
            *(uint4*)&sAh[arow * LDA + acol + 8] = vh1;
            *(uint4*)&sAl[arow * LDA + acol]     = vl0;
            *(uint4*)&sAl[arow * LDA + acol + 8] = vl1;
        }
        {
            size_t s = (size_t)(k0 + brow) * HID + hbase + bcol;
            *(uint4*)&sBh[brow * LDB + bcol]     = *(const uint4*)&w1h[s];
            *(uint4*)&sBh[brow * LDB + bcol + 8] = *(const uint4*)&w1h[s + 8];
            *(uint4*)&sBl[brow * LDB + bcol]     = *(const uint4*)&w1l[s];
            *(uint4*)&sBl[brow * LDB + bcol + 8] = *(const uint4*)&w1l[s + 8];
        }
        __syncthreads();

#pragma unroll
        for (int kk = 0; kk < KB / 16; kk++) {
            wmma::fragment<wmma::matrix_a, 16, 16, 16, __nv_bfloat16, wmma::row_major> fah[2], fal[2];
#pragma unroll
            for (int i = 0; i < 2; i++) {
                wmma::load_matrix_sync(fah[i], &sAh[(wm * 32 + i * 16) * LDA + kk * 16], LDA);
                wmma::load_matrix_sync(fal[i], &sAl[(wm * 32 + i * 16) * LDA + kk * 16], LDA);
            }
#pragma unroll
            for (int j = 0; j < 4; j++) {
                wmma::fragment<wmma::matrix_b, 16, 16, 16, __nv_bfloat16, wmma::row_major> fbh, fbl;
                wmma::load_matrix_sync(fbh, &sBh[kk * 16 * LDB + wn * 64 + j * 16], LDB);
                wmma::load_matrix_sync(fbl, &sBl[kk * 16 * LDB + wn * 64 + j * 16], LDB);
#pragma unroll
                for (int i = 0; i < 2; i++) {
                    wmma::mma_sync(acc[i][j], fah[i], fbh, acc[i][j]);
                    wmma::mma_sync(acc[i][j], fal[i], fbh, acc[i][j]);
                    wmma::mma_sync(acc[i][j], fah[i], fbl, acc[i][j]);
                }
            }
        }
    }

    // direct stores: this tile exclusively owns its 128 g_h rows (padded segs)
#pragma unroll
    for (int i = 0; i < 2; i++)
#pragma unroll
        for (int j = 0; j < 4; j++) {
            size_t ro = (size_t)(base - h0pos + wm * 32 + i * 16) * HID
                      + hbase + wn * 64 + j * 16;
            wmma::store_matrix_sync((float*)&g_h[ro], acc[i][j], HID,
                                    wmma::mem_row_major);
        }
}

// ================= GELU + in-place pack (fp32 -> bf16 hi|lo in same word) ====
__global__ void __launch_bounds__(256)
gelu_pack_kernel(const float* __restrict__ b1, int half) {
    int h0, hend;
    half_rows(half, h0, hend);
    int nquads = (hend - h0) * (HID / 4);
    int idx = blockIdx.x * blockDim.x + threadIdx.x;
    if (idx >= nquads) return;
    int rowo = idx / (HID / 4);
    int q = idx - rowo * (HID / 4);
    int pos = h0 + rowo;
    // position -> expert (8-entry scan of padded offsets)
    int e = 0;
#pragma unroll
    for (int k = 1; k < NEXP; k++) if (pos >= g_off[k]) e = k;
    const float* b1e = b1 + (size_t)e * HID + q * 4;
    size_t o = (size_t)rowo * HID + q * 4;
    float4 z4 = *(const float4*)&g_h[o];
    float zz[4] = {z4.x, z4.y, z4.z, z4.w};
    unsigned int pk[4];
#pragma unroll
    for (int i = 0; i < 4; i++) {
        float z = zz[i] + b1e[i];
        float g = 0.5f * z * (1.0f + erff(z * 0.70710678118654752f));
        __nv_bfloat16 h = __float2bfloat16(g);
        __nv_bfloat16 l = __float2bfloat16(g - __bfloat162float(h));
        unsigned short hu = *(unsigned short*)&h;
        unsigned short lu = *(unsigned short*)&l;
        pk[i] = (unsigned int)hu | ((unsigned int)lu << 16);
    }
    *(uint4*)&g_h[o] = *(uint4*)pk;
}

// ================= GEMM2: h @ w2[e] -> raw fp32 g_y (direct frag stores) =====
__global__ void __launch_bounds__(256)
gemm2_mma(int half) {
    int t, h0pos;
    if (!tile_range(half, blockIdx.x, t, h0pos)) return;
    int e = g_tile_e[t], base = g_tile_base[t], rows = g_tile_rows[t];
    int dbase = blockIdx.y * 128;

    __shared__ __align__(16) __nv_bfloat16 sAh[128 * LDA];
    __shared__ __align__(16) __nv_bfloat16 sAl[128 * LDA];
    __shared__ __align__(16) __nv_bfloat16 sBh[KB * LDB];
    __shared__ __align__(16) __nv_bfloat16 sBl[KB * LDB];

    int tid = threadIdx.x, wid = tid >> 5;
    int wm = wid & 3, wn = wid >> 2;

    const __nv_bfloat16* w2h = g_w2hi + (size_t)e * HID * DIM;
    const __nv_bfloat16* w2l = g_w2lo + (size_t)e * HID * DIM;

    wmma::fragment<wmma::accumulator, 16, 16, 16, float> acc[2][4];
#pragma unroll
    for (int i = 0; i < 2; i++)
#pragma unroll
        for (int j = 0; j < 4; j++) wmma::fill_fragment(acc[i][j], 0.f);

    int arow = tid >> 1, acol = (tid & 1) * 16;
    bool okA = (arow < rows);
    int brow = tid >> 3, bcol = (tid & 7) * 16;

    for (int c = 0; c < HID / KB; c++) {
        int k0 = c * KB;
        __syncthreads();
        {
            unsigned int hw[8], lw[8];   // 8 uint = 16 bf16 each
            if (okA) {
                size_t s = (size_t)(base - h0pos + arow) * HID + k0 + acol;
                uint4 p0 = *(const uint4*)&g_h[s];
                uint4 p1 = *(const uint4*)&g_h[s + 4];
                uint4 p2 = *(const uint4*)&g_h[s + 8];
                uint4 p3 = *(const uint4*)&g_h[s + 12];
                unsigned int w[16] = {p0.x, p0.y, p0.z, p0.w, p1.x, p1.y, p1.z, p1.w,
                                      p2.x, p2.y, p2.z, p2.w, p3.x, p3.y, p3.z, p3.w};
#pragma unroll
                for (int g = 0; g < 8; g++) {
                    hw[g] = __byte_perm(w[2 * g], w[2 * g + 1], 0x5410);
                    lw[g] = __byte_perm(w[2 * g], w[2 * g + 1], 0x7632);
                }
            } else {
#pragma unroll
                for (int g = 0; g < 8; g++) { hw[g] = 0u; lw[g] = 0u; }
            }
            *(uint4*)&sAh[arow * LDA + acol]     = *(uint4*)&hw[0];
            *(uint4*)&sAh[arow * LDA + acol + 8] = *(uint4*)&hw[4];
            *(uint4*)&sAl[arow * LDA + acol]     = *(uint4*)&lw[0];
            *(uint4*)&sAl[arow * LDA + acol + 8] = *(uint4*)&lw[4];
        }
        {
            size_t s = (size_t)(k0 + brow) * DIM + dbase + bcol;
            *(uint4*)&sBh[brow * LDB + bcol]     = *(const uint4*)&w2h[s];
            *(uint4*)&sBh[brow * LDB + bcol + 8] = *(const uint4*)&w2h[s + 8];
            *(uint4*)&sBl[brow * LDB + bcol]     = *(const uint4*)&w2l[s];
            *(uint4*)&sBl[brow * LDB + bcol + 8] = *(const uint4*)&w2l[s + 8];
        }
        __syncthreads();

#pragma unroll
        for (int kk = 0; kk < KB / 16; kk++) {
            wmma::fragment<wmma::matrix_a, 16, 16, 16, __nv_bfloat16, wmma::row_major> fah[2], fal[2];
#pragma unroll
            for (int i = 0; i < 2; i++) {
                wmma::load_matrix_sync(fah[i], &sAh[(wm * 32 + i * 16) * LDA + kk * 16], LDA);
                wmma::load_matrix_sync(fal[i], &sAl[(wm * 32 + i * 16) * LDA + kk * 16], LDA);
            }
#pragma unroll
            for (int j = 0; j < 4; j++) {
                wmma::fragment<wmma::matrix_b, 16, 16, 16, __nv_bfloat16, wmma::row_major> fbh, fbl;
                wmma::load_matrix_sync(fbh, &sBh[kk * 16 * LDB + wn * 64 + j * 16], LDB);
                wmma::load_matrix_sync(fbl, &sBl[kk * 16 * LDB + wn * 64 + j * 16], LDB);
#pragma unroll
                for (int i = 0; i < 2; i++) {
                    wmma::mma_sync(acc[i][j], fah[i], fbh, acc[i][j]);
                    wmma::mma_sync(acc[i][j], fal[i], fbh, acc[i][j]);
                    wmma::mma_sync(acc[i][j], fah[i], fbl, acc[i][j]);
                }
            }
        }
    }

#pragma unroll
    for (int i = 0; i < 2; i++)
#pragma unroll
        for (int j = 0; j < 4; j++) {
            size_t ro = (size_t)(base + wm * 32 + i * 16) * DIM
                      + dbase + wn * 64 + j * 16;
            wmma::store_matrix_sync(&g_y[ro], acc[i][j], DIM, wmma::mem_row_major);
        }
}

// ================= combine: bias + routing weight + sum =================
__global__ void combine_kernel(const float* __restrict__ b2,
                               float* __restrict__ out) {
    int idx = blockIdx.x * blockDim.x + threadIdx.x;
    if (idx >= N_TOK * (DIM / 4)) return;
    int n = idx >> 6, q = idx & 63;
    int p0 = g_tok2pos[2 * n + 0];
    int p1 = g_tok2pos[2 * n + 1];
    int e0 = g_topi[2 * n + 0];
    int e1 = g_topi[2 * n + 1];
    float w0 = g_topw[2 * n + 0];
    float w1 = g_topw[2 * n + 1];
    float4 y0 = ((const float4*)&g_y[(size_t)p0 * DIM])[q];
    float4 y1 = ((const float4*)&g_y[(size_t)p1 * DIM])[q];
    float4 c0 = ((const float4*)&b2[(size_t)e0 * DIM])[q];
    float4 c1 = ((const float4*)&b2[(size_t)e1 * DIM])[q];
    float4 r;
    r.x = w0 * (y0.x + c0.x) + w1 * (y1.x + c1.x);
    r.y = w0 * (y0.y + c0.y) + w1 * (y1.y + c1.y);
    r.z = w0 * (y0.z + c0.z) + w1 * (y1.z + c1.z);
    r.w = w0 * (y0.w + c0.w) + w1 * (y1.w + c1.w);
    ((float4*)out)[(size_t)n * 64 + q] = r;
}

// ================= launch =================
extern "C" void kernel_launch(void* const* d_in, const int* in_sizes, int n_in,
                              void* d_out, int out_size) {
    const float* x  = (const float*)d_in[0];
    const float* Wg = (const float*)d_in[1];
    const float* w1 = (const float*)d_in[2];
    const float* b1 = (const float*)d_in[3];
    const float* w2 = (const float*)d_in[4];
    const float* b2 = (const float*)d_in[5];
    float* out = (float*)d_out;

    init_kernel<<<1, 32>>>();
    gate_kernel<<<N_TOK / 4, 128>>>(x, Wg);
    prep_kernel<<<1, 1>>>();
    scatter_kernel<<<NASSIGN / 256, 256>>>();
    conv_x_kernel<<<(N_TOK * DIM / 8) / 256, 256>>>(x);
    conv_w1_kernel<<<(NEXP * DIM * HID / 8) / 256, 256>>>(w1);
    conv_w2_kernel<<<(NEXP * HID * DIM / 8) / 256, 256>>>(w2);
    int gelu_blocks = (HROWS * (HID / 4) + 255) / 256;
    for (int half = 0; half < 2; half++) {
        gemm1_mma<<<dim3(HALF_TILES, HID / 128), 256>>>(half);
        gelu_pack_kernel<<<gelu_blocks, 256>>>(b1, half);
        gemm2_mma<<<dim3(HALF_TILES, DIM / 128), 256>>>(half);
    }
    combine_kernel<<<(N_TOK * (DIM / 4)) / 256, 256>>>(b2, out);
}

// round 14
// speedup vs baseline: 1.6914x; 1.0029x over previous
#include <cuda_runtime.h>
#include <cuda_bf16.h>
#include <mma.h>
#include <math.h>
#include <stdint.h>

using namespace nvcuda;

// Problem constants
#define N_TOK 16384
#define DIM   256
#define NEXP  8
#define HID   512
#define TOPK  2
#define NASSIGN (N_TOK * TOPK)            // 32768
#define NPAD (NASSIGN + NEXP * 128)       // 33792 padded positions
#define MAX_TILES (NPAD / 128)            // 264
#define HALF_TILES 136
#define HROWS 17408                       // per-half h rows (136*128)

// GEMM tiling: CTA tile 128x128, K chunk 32, wmma 16x16x16.
#define KB   32
#define LDA  40        // A smem leading dim (bf16)
#define LDB  136       // B smem leading dim (bf16)

// ================= device scratch =================
__device__ int   g_counts[NEXP];
__device__ int   g_cursor[NEXP];
__device__ int   g_off[NEXP + 1];
__device__ int   g_ntiles;
__device__ int   g_tile_e[MAX_TILES];
__device__ int   g_tile_base[MAX_TILES];
__device__ int   g_tile_rows[MAX_TILES];

__device__ int   g_topi[NASSIGN];
__device__ float g_topw[NASSIGN];
__device__ int   g_ptok[NPAD];
__device__ int   g_tok2pos[NASSIGN];

__device__ __nv_bfloat16 g_xhi[(size_t)N_TOK * DIM];
__device__ __nv_bfloat16 g_xlo[(size_t)N_TOK * DIM];
__device__ __nv_bfloat16 g_w1hi[(size_t)NEXP * DIM * HID];  // [E][D][H]
__device__ __nv_bfloat16 g_w1lo[(size_t)NEXP * DIM * HID];
__device__ __nv_bfloat16 g_w2hi[(size_t)NEXP * HID * DIM];  // [E][H][D]
__device__ __nv_bfloat16 g_w2lo[(size_t)NEXP * HID * DIM];
// g_h: raw fp32 from GEMM1, then packed (bf16 hi | bf16 lo) in place by gelu
__device__ unsigned int g_h[(size_t)HROWS * HID];
__device__ float g_y[(size_t)NPAD * DIM];

// ================= kernel 0: init =================
__global__ void init_kernel() {
    int t = threadIdx.x;
    if (t < NEXP) { g_counts[t] = 0; g_cursor[t] = 0; }
}

// ================= kernel 1: gate (top-2 + softmax) =================
__global__ void gate_kernel(const float* __restrict__ x,
                            const float* __restrict__ Wg) {
    __shared__ float sWg[NEXP][DIM];
    int tid = threadIdx.x;
    for (int i = tid; i < DIM * NEXP; i += blockDim.x) {
        int e = i & (NEXP - 1);
        int d = i >> 3;
        sWg[e][d] = Wg[i];
    }
    __syncthreads();

    int warp = tid >> 5, lane = tid & 31;
    int n = blockIdx.x * 4 + warp;
    if (n >= N_TOK) return;

    float lg[NEXP];
#pragma unroll
    for (int e = 0; e < NEXP; e++) lg[e] = 0.f;
#pragma unroll
    for (int j = 0; j < 8; j++) {
        int d = lane + 32 * j;
        float xv = x[(size_t)n * DIM + d];
#pragma unroll
        for (int e = 0; e < NEXP; e++) lg[e] += xv * sWg[e][d];
    }
#pragma unroll
    for (int e = 0; e < NEXP; e++)
#pragma unroll
        for (int o = 16; o > 0; o >>= 1)
            lg[e] += __shfl_xor_sync(0xffffffffu, lg[e], o);

    if (lane == 0) {
        float m1 = lg[0]; int i1 = 0;
#pragma unroll
        for (int e = 1; e < NEXP; e++) if (lg[e] > m1) { m1 = lg[e]; i1 = e; }
        float m2 = -1e30f; int i2 = 0;
#pragma unroll
        for (int e = 0; e < NEXP; e++)
            if (e != i1 && lg[e] > m2) { m2 = lg[e]; i2 = e; }
        float p2 = expf(m2 - m1);
        float inv = 1.f / (1.f + p2);
        g_topi[2 * n + 0] = i1;  g_topw[2 * n + 0] = inv;
        g_topi[2 * n + 1] = i2;  g_topw[2 * n + 1] = p2 * inv;
        atomicAdd(&g_counts[i1], 1);
        atomicAdd(&g_counts[i2], 1);
    }
}

// ================= kernel 2: prefix (128-aligned) + tile descriptors ========
__global__ void prep_kernel() {
    int off = 0;
    for (int e = 0; e < NEXP; e++) {
        g_off[e] = off;
        off += (g_counts[e] + 127) & ~127;
    }
    g_off[NEXP] = off;
    int t = 0;
    for (int e = 0; e < NEXP; e++) {
        int cnt = g_counts[e];
        for (int s = 0; s < cnt; s += 128) {
            g_tile_e[t] = e;
            g_tile_base[t] = g_off[e] + s;
            g_tile_rows[t] = min(128, cnt - s);
            t++;
        }
    }
    g_ntiles = t;
}

// ================= kernel 3: scatter =================
__global__ void scatter_kernel() {
    int idx = blockIdx.x * blockDim.x + threadIdx.x;
    if (idx >= NASSIGN) return;
    int e = g_topi[idx];
    int pos = g_off[e] + atomicAdd(&g_cursor[e], 1);
    g_ptok[pos] = idx >> 1;
    g_tok2pos[idx] = pos;
}

// ===== split helper =====
__device__ __forceinline__ void split8(const float* v,
                                       __nv_bfloat16* h, __nv_bfloat16* l) {
#pragma unroll
    for (int i = 0; i < 8; i++) {
        h[i] = __float2bfloat16(v[i]);
        l[i] = __float2bfloat16(v[i] - __bfloat162float(h[i]));
    }
}

// ================= conv kernels (globals referenced INSIDE device code) ======
__global__ void conv_x_kernel(const float* __restrict__ src) {
    int idx = blockIdx.x * blockDim.x + threadIdx.x;
    if (idx >= N_TOK * DIM / 8) return;
    size_t b8 = (size_t)idx * 8;
    float4 a = *(const float4*)&src[b8];
    float4 b = *(const float4*)&src[b8 + 4];
    float v[8] = {a.x, a.y, a.z, a.w, b.x, b.y, b.z, b.w};
    __align__(16) __nv_bfloat16 h[8], l[8];
    split8(v, h, l);
    *(uint4*)&g_xhi[b8] = *(uint4*)h;
    *(uint4*)&g_xlo[b8] = *(uint4*)l;
}

__global__ void conv_w1_kernel(const float* __restrict__ src) {
    int idx = blockIdx.x * blockDim.x + threadIdx.x;
    if (idx >= NEXP * DIM * HID / 8) return;
    size_t b8 = (size_t)idx * 8;
    float4 a = *(const float4*)&src[b8];
    float4 b = *(const float4*)&src[b8 + 4];
    float v[8] = {a.x, a.y, a.z, a.w, b.x, b.y, b.z, b.w};
    __align__(16) __nv_bfloat16 h[8], l[8];
    split8(v, h, l);
    *(uint4*)&g_w1hi[b8] = *(uint4*)h;
    *(uint4*)&g_w1lo[b8] = *(uint4*)l;
}

__global__ void conv_w2_kernel(const float* __restrict__ src) {
    int idx = blockIdx.x * blockDim.x + threadIdx.x;
    if (idx >= NEXP * HID * DIM / 8) return;
    size_t b8 = (size_t)idx * 8;
    float4 a = *(const float4*)&src[b8];
    float4 b = *(const float4*)&src[b8 + 4];
    float v[8] = {a.x, a.y, a.z, a.w, b.x, b.y, b.z, b.w};
    __align__(16) __nv_bfloat16 h[8], l[8];
    split8(v, h, l);
    *(uint4*)&g_w2hi[b8] = *(uint4*)h;
    *(uint4*)&g_w2lo[b8] = *(uint4*)l;
}

// ================= half-range helpers =================
__device__ __forceinline__ bool tile_range(int half, int bx,
                                           int& t, int& h0pos) {
    int Hs = (g_ntiles + 1) >> 1;
    int t0 = half ? Hs : 0;
    int tend = half ? g_ntiles : Hs;
    t = t0 + bx;
    if (t >= tend) return false;
    h0pos = g_tile_base[t0];
    return true;
}
__device__ __forceinline__ void half_rows(int half, int& h0, int& hend) {
    int Hs = (g_ntiles + 1) >> 1;
    h0 = half ? g_tile_base[Hs] : 0;
    hend = half ? g_off[NEXP] : g_tile_base[Hs];
}

// ================= GEMM1: x @ w1[e] -> raw fp32 g_h ==========================
// register-staged prefetch: chunk c+1 loads issued before chunk c's MMA.
__global__ void __launch_bounds__(256)
gemm1_mma(int half) {
    int t, h0pos;
    if (!tile_range(half, blockIdx.x, t, h0pos)) return;
    int e = g_tile_e[t], base = g_tile_base[t], rows = g_tile_rows[t];
    int hbase = blockIdx.y * 128;

    __shared__ __align__(16) __nv_bfloat16 sAh[128 * LDA];
    __shared__ __align__(16) __nv_bfloat16 sAl[128 * LDA];
    __shared__ __align__(16) __nv_bfloat16 sBh[KB * LDB];
    __shared__ __align__(16) __nv_bfloat16 sBl[KB * LDB];

    int tid = threadIdx.x, wid = tid >> 5;
    int wm = wid & 3, wn = wid >> 2;

    const __nv_bfloat16* w1h = g_w1hi + (size_t)e * DIM * HID;
    const __nv_bfloat16* w1l = g_w1lo + (size_t)e * DIM * HID;

    wmma::fragment<wmma::accumulator, 16, 16, 16, float> acc[2][4];
#pragma unroll
    for (int i = 0; i < 2; i++)
#pragma unroll
        for (int j = 0; j < 4; j++) wmma::fill_fragment(acc[i][j], 0.f);

    int arow = tid >> 1, acol = (tid & 1) * 16;
    int tok = (arow < rows) ? g_ptok[base + arow] : -1;
    int brow = tid >> 3, bcol = (tid & 7) * 16;

    const int NC = DIM / KB;
    uint4 rAh0, rAh1, rAl0, rAl1, rB0, rB1, rB2, rB3;

    // prefetch chunk 0
    {
        rAh0 = rAh1 = rAl0 = rAl1 = make_uint4(0, 0, 0, 0);
        if (tok >= 0) {
            size_t s = (size_t)tok * DIM + acol;
            rAh0 = *(const uint4*)&g_xhi[s];
            rAh1 = *(const uint4*)&g_xhi[s + 8];
            rAl0 = *(const uint4*)&g_xlo[s];
            rAl1 = *(const uint4*)&g_xlo[s + 8];
        }
        size_t sB = (size_t)brow * HID + hbase + bcol;
        rB0 = *(const uint4*)&w1h[sB];
        rB1 = *(const uint4*)&w1h[sB + 8];
        rB2 = *(const uint4*)&w1l[sB];
        rB3 = *(const uint4*)&w1l[sB + 8];
    }

    for (int c = 0; c < NC; c++) {
        __syncthreads();   // smem free (consumed by previous MMA)
        *(uint4*)&sAh[arow * LDA + acol]     = rAh0;
        *(uint4*)&sAh[arow * LDA + acol + 8] = rAh1;
        *(uint4*)&sAl[arow * LDA + acol]     = rAl0;
        *(uint4*)&sAl[arow * LDA + acol + 8] = rAl1;
        *(uint4*)&sBh[brow * LDB + bcol]     = rB0;
        *(uint4*)&sBh[brow * LDB + bcol + 8] = rB1;
        *(uint4*)&sBl[brow * LDB + bcol]     = rB2;
        *(uint4*)&sBl[brow * LDB + bcol + 8] = rB3;
        __syncthreads();   // smem ready

        if (c + 1 < NC) {  // issue next chunk's LDGs; in flight during MMA
            int k0 = (c + 1) * KB;
            rAh0 = rAh1 = rAl0 = rAl1 = make_uint4(0, 0, 0, 0);
            if (tok >= 0) {
                size_t s = (size_t)tok * DIM + k0 + acol;
                rAh0 = *(const uint4*)&g_xhi[s];
                rAh1 = *(const uint4*)&g_xhi[s + 8];
                rAl0 = *(const uint4*)&g_xlo[s];
                rAl1 = *(const uint4*)&g_xlo[s + 8];
            }
            size_t sB = (size_t)(k0 + brow) * HID + hbase + bcol;
            rB0 = *(const uint4*)&w1h[sB];
            rB1 = *(const uint4*)&w1h[sB + 8];
            rB2 = *(const uint4*)&w1l[sB];
            rB3 = *(const uint4*)&w1l[sB + 8];
        }

#pragma unroll
        for (int kk = 0; kk < KB / 16; kk++) {
            wmma::fragment<wmma::matrix_a, 16, 16, 16, __nv_bfloat16, wmma::row_major> fah[2], fal[2];
#pragma unroll
            for (int i = 0; i < 2; i++) {
                wmma::load_matrix_sync(fah[i], &sAh[(wm * 32 + i * 16) * LDA + kk * 16], LDA);
                wmma::load_matrix_sync(fal[i], &sAl[(wm * 32 + i * 16) * LDA + kk * 16], LDA);
            }
#pragma unroll
            for (int j = 0; j < 4; j++) {
                wmma::fragment<wmma::matrix_b, 16, 16, 16, __nv_bfloat16, wmma::row_major> fbh, fbl;
                wmma::load_matrix_sync(fbh, &sBh[kk * 16 * LDB + wn * 64 + j * 16], LDB);
                wmma::load_matrix_sync(fbl, &sBl[kk * 16 * LDB + wn * 64 + j * 16], LDB);
#pragma unroll
                for (int i = 0; i < 2; i++) {
                    wmma::mma_sync(acc[i][j], fah[i], fbh, acc[i][j]);
                    wmma::mma_sync(acc[i][j], fal[i], fbh, acc[i][j]);
                    wmma::mma_sync(acc[i][j], fah[i], fbl, acc[i][j]);
                }
            }
        }
    }

    // direct stores: tile exclusively owns its 128 g_h rows (padded segments)
#pragma unroll
    for (int i = 0; i < 2; i++)
#pragma unroll
        for (int j = 0; j < 4; j++) {
            size_t ro = (size_t)(base - h0pos + wm * 32 + i * 16) * HID
                      + hbase + wn * 64 + j * 16;
            wmma::store_matrix_sync((float*)&g_h[ro], acc[i][j], HID,
                                    wmma::mem_row_major);
        }
}

// ================= GELU + in-place pack (fp32 -> bf16 hi|lo) =================
__global__ void __launch_bounds__(256)
gelu_pack_kernel(const float* __restrict__ b1, int half) {
    int h0, hend;
    half_rows(half, h0, hend);
    int nquads = (hend - h0) * (HID / 4);
    int idx = blockIdx.x * blockDim.x + threadIdx.x;
    if (idx >= nquads) return;
    int rowo = idx / (HID / 4);
    int q = idx - rowo * (HID / 4);
    int pos = h0 + rowo;
    int e = 0;
#pragma unroll
    for (int k = 1; k < NEXP; k++) if (pos >= g_off[k]) e = k;
    const float* b1e = b1 + (size_t)e * HID + q * 4;
    size_t o = (size_t)rowo * HID + q * 4;
    float4 z4 = *(const float4*)&g_h[o];
    float zz[4] = {z4.x, z4.y, z4.z, z4.w};
    unsigned int pk[4];
#pragma unroll
    for (int i = 0; i < 4; i++) {
        float z = zz[i] + b1e[i];
        float g = 0.5f * z * (1.0f + erff(z * 0.70710678118654752f));
        __nv_bfloat16 h = __float2bfloat16(g);
        __nv_bfloat16 l = __float2bfloat16(g - __bfloat162float(h));
        unsigned short hu = *(unsigned short*)&h;
        unsigned short lu = *(unsigned short*)&l;
        pk[i] = (unsigned int)hu | ((unsigned int)lu << 16);
    }
    *(uint4*)&g_h[o] = *(uint4*)pk;
}

// ================= GEMM2: h @ w2[e] -> raw fp32 g_y ==========================
__global__ void __launch_bounds__(256)
gemm2_mma(int half) {
    int t, h0pos;
    if (!tile_range(half, blockIdx.x, t, h0pos)) return;
    int e = g_tile_e[t], base = g_tile_base[t], rows = g_tile_rows[t];
    int dbase = blockIdx.y * 128;

    __shared__ __align__(16) __nv_bfloat16 sAh[128 * LDA];
    __shared__ __align__(16) __nv_bfloat16 sAl[128 * LDA];
    __shared__ __align__(16) __nv_bfloat16 sBh[KB * LDB];
    __shared__ __align__(16) __nv_bfloat16 sBl[KB * LDB];

    int tid = threadIdx.x, wid = tid >> 5;
    int wm = wid & 3, wn = wid >> 2;

    const __nv_bfloat16* w2h = g_w2hi + (size_t)e * HID * DIM;
    const __nv_bfloat16* w2l = g_w2lo + (size_t)e * HID * DIM;

    wmma::fragment<wmma::accumulator, 16, 16, 16, float> acc[2][4];
#pragma unroll
    for (int i = 0; i < 2; i++)
#pragma unroll
        for (int j = 0; j < 4; j++) wmma::fill_fragment(acc[i][j], 0.f);

    int arow = tid >> 1, acol = (tid & 1) * 16;
    bool okA = (arow < rows);
    int brow = tid >> 3, bcol = (tid & 7) * 16;

    const int NC = HID / KB;
    uint4 p0, p1, p2, p3, rB0, rB1, rB2, rB3;

    // prefetch chunk 0
    {
        p0 = p1 = p2 = p3 = make_uint4(0, 0, 0, 0);
        if (okA) {
            size_t s = (size_t)(base - h0pos + arow) * HID + acol;
            p0 = *(const uint4*)&g_h[s];
            p1 = *(const uint4*)&g_h[s + 4];
            p2 = *(const uint4*)&g_h[s + 8];
            p3 = *(const uint4*)&g_h[s + 12];
        }
        size_t sB = (size_t)brow * DIM + dbase + bcol;
        rB0 = *(const uint4*)&w2h[sB];
        rB1 = *(const uint4*)&w2h[sB + 8];
        rB2 = *(const uint4*)&w2l[sB];
        rB3 = *(const uint4*)&w2l[sB + 8];
    }

    for (int c = 0; c < NC; c++) {
        __syncthreads();
        {
            unsigned int w[16] = {p0.x, p0.y, p0.z, p0.w, p1.x, p1.y, p1.z, p1.w,
                                  p2.x, p2.y, p2.z, p2.w, p3.x, p3.y, p3.z, p3.w};
            unsigned int hw[8], lw[8];
#pragma unroll
            for (int g = 0; g < 8; g++) {
                hw[g] = __byte_perm(w[2 * g], w[2 * g + 1], 0x5410);
                lw[g] = __byte_perm(w[2 * g], w[2 * g + 1], 0x7632);
            }
            *(uint4*)&sAh[arow * LDA + acol]     = *(uint4*)&hw[0];
            *(uint4*)&sAh[arow * LDA + acol + 8] = *(uint4*)&hw[4];
            *(uint4*)&sAl[arow * LDA + acol]     = *(uint4*)&lw[0];
            *(uint4*)&sAl[arow * LDA + acol + 8] = *(uint4*)&lw[4];
        }
        *(uint4*)&sBh[brow * LDB + bcol]     = rB0;
        *(uint4*)&sBh[brow * LDB + bcol + 8] = rB1;
        *(uint4*)&sBl[brow * LDB + bcol]     = rB2;
        *(uint4*)&sBl[brow * LDB + bcol + 8] = rB3;
        __syncthreads();

        if (c + 1 < NC) {
            int k0 = (c + 1) * KB;
            p0 = p1 = p2 = p3 = make_uint4(0, 0, 0, 0);
            if (okA) {
                size_t s = (size_t)(base - h0pos + arow) * HID + k0 + acol;
                p0 = *(const uint4*)&g_h[s];
                p1 = *(const uint4*)&g_h[s + 4];
                p2 = *(const uint4*)&g_h[s + 8];
                p3 = *(const uint4*)&g_h[s + 12];
            }
            size_t sB = (size_t)(k0 + brow) * DIM + dbase + bcol;
            rB0 = *(const uint4*)&w2h[sB];
            rB1 = *(const uint4*)&w2h[sB + 8];
            rB2 = *(const uint4*)&w2l[sB];
            rB3 = *(const uint4*)&w2l[sB + 8];
        }

#pragma unroll
        for (int kk = 0; kk < KB / 16; kk++) {
            wmma::fragment<wmma::matrix_a, 16, 16, 16, __nv_bfloat16, wmma::row_major> fah[2], fal[2];
#pragma unroll
            for (int i = 0; i < 2; i++) {
                wmma::load_matrix_sync(fah[i], &sAh[(wm * 32 + i * 16) * LDA + kk * 16], LDA);
                wmma::load_matrix_sync(fal[i], &sAl[(wm * 32 + i * 16) * LDA + kk * 16], LDA);
            }
#pragma unroll
            for (int j = 0; j < 4; j++) {
                wmma::fragment<wmma::matrix_b, 16, 16, 16, __nv_bfloat16, wmma::row_major> fbh, fbl;
                wmma::load_matrix_sync(fbh, &sBh[kk * 16 * LDB + wn * 64 + j * 16], LDB);
                wmma::load_matrix_sync(fbl, &sBl[kk * 16 * LDB + wn * 64 + j * 16], LDB);
#pragma unroll
                for (int i = 0; i < 2; i++) {
                    wmma::mma_sync(acc[i][j], fah[i], fbh, acc[i][j]);
                    wmma::mma_sync(acc[i][j], fal[i], fbh, acc[i][j]);
                    wmma::mma_sync(acc[i][j], fah[i], fbl, acc[i][j]);
                }
            }
        }
    }

#pragma unroll
    for (int i = 0; i < 2; i++)
#pragma unroll
        for (int j = 0; j < 4; j++) {
            size_t ro = (size_t)(base + wm * 32 + i * 16) * DIM
                      + dbase + wn * 64 + j * 16;
            wmma::store_matrix_sync(&g_y[ro], acc[i][j], DIM, wmma::mem_row_major);
        }
}

// ================= combine: bias + routing weight + sum =================
__global__ void combine_kernel(const float* __restrict__ b2,
                               float* __restrict__ out) {
    int idx = blockIdx.x * blockDim.x + threadIdx.x;
    if (idx >= N_TOK * (DIM / 4)) return;
    int n = idx >> 6, q = idx & 63;
    int p0 = g_tok2pos[2 * n + 0];
    int p1 = g_tok2pos[2 * n + 1];
    int e0 = g_topi[2 * n + 0];
    int e1 = g_topi[2 * n + 1];
    float w0 = g_topw[2 * n + 0];
    float w1 = g_topw[2 * n + 1];
    float4 y0 = ((const float4*)&g_y[(size_t)p0 * DIM])[q];
    float4 y1 = ((const float4*)&g_y[(size_t)p1 * DIM])[q];
    float4 c0 = ((const float4*)&b2[(size_t)e0 * DIM])[q];
    float4 c1 = ((const float4*)&b2[(size_t)e1 * DIM])[q];
    float4 r;
    r.x = w0 * (y0.x + c0.x) + w1 * (y1.x + c1.x);
    r.y = w0 * (y0.y + c0.y) + w1 * (y1.y + c1.y);
    r.z = w0 * (y0.z + c0.z) + w1 * (y1.z + c1.z);
    r.w = w0 * (y0.w + c0.w) + w1 * (y1.w + c1.w);
    ((float4*)out)[(size_t)n * 64 + q] = r;
}

// ================= launch =================
extern "C" void kernel_launch(void* const* d_in, const int* in_sizes, int n_in,
                              void* d_out, int out_size) {
    const float* x  = (const float*)d_in[0];
    const float* Wg = (const float*)d_in[1];
    const float* w1 = (const float*)d_in[2];
    const float* b1 = (const float*)d_in[3];
    const float* w2 = (const float*)d_in[4];
    const float* b2 = (const float*)d_in[5];
    float* out = (float*)d_out;

    init_kernel<<<1, 32>>>();
    gate_kernel<<<N_TOK / 4, 128>>>(x, Wg);
    prep_kernel<<<1, 1>>>();
    scatter_kernel<<<NASSIGN / 256, 256>>>();
    conv_x_kernel<<<(N_TOK * DIM / 8) / 256, 256>>>(x);
    conv_w1_kernel<<<(NEXP * DIM * HID / 8) / 256, 256>>>(w1);
    conv_w2_kernel<<<(NEXP * HID * DIM / 8) / 256, 256>>>(w2);
    int gelu_blocks = (HROWS * (HID / 4) + 255) / 256;
    for (int half = 0; half < 2; half++) {
        gemm1_mma<<<dim3(HALF_TILES, HID / 128), 256>>>(half);
        gelu_pack_kernel<<<gelu_blocks, 256>>>(b1, half);
        gemm2_mma<<<dim3(HALF_TILES, DIM / 128), 256>>>(half);
    }
    combine_kernel<<<(N_TOK * (DIM / 4)) / 256, 256>>>(b2, out);
}